// round 12
// baseline (speedup 1.0000x reference)
#include <cuda_runtime.h>
#include <cuda_fp16.h>
#include <cstdint>

// GaussianMixture NLL: N=65536 samples (2D), M=1024 mixtures.  SPARSITY == 0.
// nll = -sum_n log( sum_m exp(wlog_m - qf(n,m)) )
//
// v12: FMA-pipe relief. v10 structure, but:
//  - c5+BIAS folded ADDITIVELY as the Horner seed:
//      p = hfma2(C0,xx,C5); p = hfma2(C1,xy,p); ... p = hfma2(C4,y,p)
//    -> still 5 FMA-pipe ops, but the accumulate becomes
//      acc = hadd2(acc, ex2(p))        // HADD2 rides the (idle) ALU pipe
//    dropping FMA-pipe occupancy from 12 -> 10 cyc per (pair,sample) unit.
//  Ranges: p in [-14,+2] (log2, biased), e <= 4, 8-term fp16 chunk <= 32,
//  flushed to fp32 (scheme validated at 3.3e-4 in R8).
//  TPB=256: 8 warps = 8 mixture-eighths (64 pairs), SPT=4 -> grid=512.

#define M_MIX   1024
#define NPAIR   (M_MIX / 2)      // 512
#define EPAIRS  (NPAIR / 8)      // 64 pairs per warp-eighth
#define TPB     256
#define SPT     4
#define SAMP_PER_BLK  128        // 32 lanes * 4 samples
#define BIAS    8.0f             // log2-domain bias folded into c5

// pair records: {c0,c1,c2,c3} {c4,c5b,pad,pad} as half2 words -> 32B/pair
__device__ uint4 g_params[NPAIR * 2];

// ---------- helpers ----------
__device__ __forceinline__ __half2 u2h2(unsigned int u) {
    __half2 h; *(unsigned int*)&h = u; return h;
}
__device__ __forceinline__ unsigned int h2u(__half2 h) {
    return *(unsigned int*)&h;
}
__device__ __forceinline__ __half2 hex2(__half2 x) {
    unsigned int y;
    asm("ex2.approx.f16x2 %0, %1;" : "=r"(y) : "r"(h2u(x)));
    return u2h2(y);
}

// ---------- prep: log_softmax(w) + fp16 coefficient records ----------
__global__ void gmm_prep(const float* __restrict__ mu,
                         const float* __restrict__ sigma_log,
                         const float* __restrict__ theta,
                         const float* __restrict__ w,
                         float* __restrict__ out) {
    __shared__ float red[32];
    __shared__ float stage[6][M_MIX];     // scalar c0..c5b per mixture
    const int m    = threadIdx.x;
    const int lane = m & 31;
    const int wid  = m >> 5;

    const float wi = w[m];

    // block max via shuffle
    float v = wi;
    #pragma unroll
    for (int o = 16; o > 0; o >>= 1) v = fmaxf(v, __shfl_xor_sync(~0u, v, o));
    if (lane == 0) red[wid] = v;
    __syncthreads();
    float wmax = red[lane & 31];
    #pragma unroll
    for (int o = 16; o > 0; o >>= 1) wmax = fmaxf(wmax, __shfl_xor_sync(~0u, wmax, o));
    wmax = __shfl_sync(~0u, wmax, 0);
    __syncthreads();

    // block sum(exp) via shuffle
    float e = __expf(wi - wmax);
    #pragma unroll
    for (int o = 16; o > 0; o >>= 1) e += __shfl_xor_sync(~0u, e, o);
    if (lane == 0) red[wid] = e;
    __syncthreads();
    float esum = red[lane & 31];
    #pragma unroll
    for (int o = 16; o > 0; o >>= 1) esum += __shfl_xor_sync(~0u, esum, o);
    esum = __shfl_sync(~0u, esum, 0);

    const float logZ = wmax + __logf(esum);

    const float sl0 = sigma_log[2 * m + 0];
    const float sl1 = sigma_log[2 * m + 1];
    const float a = __expf(-2.0f * sl0);
    const float b = __expf(-2.0f * sl1);
    float s, c;
    __sincosf(theta[m], &s, &c);

    const float g11 = a * c * c + b * s * s;
    const float g12 = (a - b) * c * s;
    const float g22 = a * s * s + b * c * c;
    const float wlog = wi - logZ - sl0 - sl1;

    const float mx = mu[2 * m + 0];
    const float my = mu[2 * m + 1];

    const float L2E = 1.4426950408889634f;

    const float qmu = g11 * mx * mx + 2.0f * g12 * mx * my + g22 * my * my;

    stage[0][m] = -L2E * g11;                          // c0
    stage[1][m] = -L2E * 2.0f * g12;                   // c1
    stage[2][m] = -L2E * g22;                          // c2
    stage[3][m] =  L2E * 2.0f * (g11 * mx + g12 * my); // c3
    stage[4][m] =  L2E * 2.0f * (g12 * mx + g22 * my); // c4
    stage[5][m] =  L2E * (wlog - qmu) + BIAS;          // c5 + BIAS (additive)
    __syncthreads();

    // pack pair records (threads 0..511)
    if (m < NPAIR) {
        const int m0 = 2 * m, m1 = 2 * m + 1;
        uint4 r0, r1;
        r0.x = h2u(__floats2half2_rn(stage[0][m0], stage[0][m1]));
        r0.y = h2u(__floats2half2_rn(stage[1][m0], stage[1][m1]));
        r0.z = h2u(__floats2half2_rn(stage[2][m0], stage[2][m1]));
        r0.w = h2u(__floats2half2_rn(stage[3][m0], stage[3][m1]));
        r1.x = h2u(__floats2half2_rn(stage[4][m0], stage[4][m1]));
        r1.y = h2u(__floats2half2_rn(stage[5][m0], stage[5][m1]));
        r1.z = 0u; r1.w = 0u;
        g_params[2 * m + 0] = r0;
        g_params[2 * m + 1] = r1;
    }

    if (m == 0) out[0] = 0.0f;        // re-zeroed every replay -> deterministic
}

// ---------- hot loop ----------
__global__ void __launch_bounds__(TPB, 4) gmm_main(const float* __restrict__ sample,
                                                   float* __restrict__ out,
                                                   int N) {
    __shared__ __align__(16) uint4 sp[NPAIR * 2];      // 16 KB coefficient records
    __shared__ float partial[8][SAMP_PER_BLK];
    __shared__ float warpsum[8];

    const int tid  = threadIdx.x;
    const int lane = tid & 31;
    const int wid  = tid >> 5;

    // cooperative param load (1024 uint4)
    #pragma unroll
    for (int i = tid; i < NPAIR * 2; i += TPB) sp[i] = g_params[i];
    __syncthreads();

    const int base = blockIdx.x * SAMP_PER_BLK;

    // per-sample fp16x2 monomials (value broadcast to both lanes)
    __half2 hxx[SPT], hxy[SPT], hyy[SPT], hx[SPT], hy[SPT];
    __half2 acch[SPT];
    float accF[SPT];
    #pragma unroll
    for (int k = 0; k < SPT; ++k) {
        const int idx = base + k * 32 + lane;   // coalesced per k
        float x = 0.0f, y = 0.0f;
        if (idx < N) {
            const float2 sv = ((const float2*)sample)[idx];
            x = sv.x; y = sv.y;
        }
        hxx[k] = __float2half2_rn(x * x);
        hxy[k] = __float2half2_rn(x * y);
        hyy[k] = __float2half2_rn(y * y);
        hx[k]  = __float2half2_rn(x);
        hy[k]  = __float2half2_rn(y);
        accF[k] = 0.0f;
    }

    const uint4* ep = sp + wid * EPAIRS * 2;   // this warp's eighth

    // 8 chunks of 8 pairs; fp16x2 accumulate within a chunk, fp32 flush after
    for (int jc = 0; jc < EPAIRS; jc += 8) {
        #pragma unroll
        for (int k = 0; k < SPT; ++k) acch[k] = u2h2(0u);

        #pragma unroll
        for (int jj = 0; jj < 8; ++jj) {
            const uint4 r0 = ep[(jc + jj) * 2 + 0];
            const uint4 r1 = ep[(jc + jj) * 2 + 1];
            const __half2 C0 = u2h2(r0.x), C1 = u2h2(r0.y);
            const __half2 C2 = u2h2(r0.z), C3 = u2h2(r0.w);
            const __half2 C4 = u2h2(r1.x), C5 = u2h2(r1.y);

            #pragma unroll
            for (int k = 0; k < SPT; ++k) {
                __half2 p = __hfma2(C0, hxx[k], C5);   // seed with c5+BIAS
                p = __hfma2(C1, hxy[k], p);
                p = __hfma2(C2, hyy[k], p);
                p = __hfma2(C3, hx[k],  p);
                p = __hfma2(C4, hy[k],  p);            // p in [-14,+2]
                acch[k] = __hadd2(acch[k], hex2(p));   // HADD2 -> ALU pipe
            }
        }

        #pragma unroll
        for (int k = 0; k < SPT; ++k) {
            const float2 f = __half22float2(acch[k]);
            accF[k] += f.x + f.y;
        }
    }

    #pragma unroll
    for (int k = 0; k < SPT; ++k)
        partial[wid][k * 32 + lane] = accF[k];
    __syncthreads();

    // combine eighths; one sample per thread (tid < 128)
    float nll_i = 0.0f;
    if (tid < SAMP_PER_BLK) {
        const int sidx = base + tid;
        if (sidx < N) {
            float tot = 0.0f;
            #pragma unroll
            for (int q = 0; q < 8; ++q) tot += partial[q][tid];
            // tot = 2^BIAS * true_sum
            nll_i = 0.69314718055994531f * (BIAS - __log2f(tot));
        }
    }

    // block reduce
    #pragma unroll
    for (int o = 16; o > 0; o >>= 1)
        nll_i += __shfl_xor_sync(0xffffffffu, nll_i, o);
    if (lane == 0) warpsum[wid] = nll_i;
    __syncthreads();

    if (tid == 0) {
        float v = 0.0f;
        #pragma unroll
        for (int i = 0; i < 8; ++i) v += warpsum[i];
        atomicAdd(out, v);
    }
}

extern "C" void kernel_launch(void* const* d_in, const int* in_sizes, int n_in,
                              void* d_out, int out_size) {
    const float* sample    = (const float*)d_in[0];
    const float* mu        = (const float*)d_in[1];
    const float* sigma_log = (const float*)d_in[2];
    const float* theta     = (const float*)d_in[3];
    const float* w         = (const float*)d_in[4];
    float* out = (float*)d_out;

    const int N = in_sizes[0] / 2;
    const int grid = (N + SAMP_PER_BLK - 1) / SAMP_PER_BLK;

    gmm_prep<<<1, M_MIX>>>(mu, sigma_log, theta, w, out);
    gmm_main<<<grid, TPB>>>(sample, out, N);
}

// round 13
// speedup vs baseline: 1.0111x; 1.0111x over previous
#include <cuda_runtime.h>
#include <cuda_fp16.h>
#include <cstdint>

// GaussianMixture NLL: N=65536 samples (2D), M=1024 mixtures.  SPARSITY == 0.
// nll = -sum_n log( sum_m exp(wlog_m - qf(n,m)) )
//
// v13: issue-efficiency push. v12 math (fp16x2 poly, additive c5+BIAS seed,
//  ex2.approx.f16x2, chunk-of-8 fp16 accumulation flushed to fp32) with:
//   - SPT=5 independent sample-chains per thread (more ILP, LDS /5)
//   - launch_bounds(256,3): reg cap ~85 so ptxas can prefetch coefficient
//     LDS across chunk iterations (was hard-capped at 64 regs)
//   - SAMP_PER_BLK=160 -> grid=410 < 444 (3 CTA/SM): all CTAs co-resident,
//     single wave, ~22 warps/SM.

#define M_MIX   1024
#define NPAIR   (M_MIX / 2)      // 512
#define EPAIRS  (NPAIR / 8)      // 64 pairs per warp-eighth
#define TPB     256
#define SPT     5
#define SAMP_PER_BLK  160        // 32 lanes * 5 samples
#define BIAS    8.0f             // log2-domain bias folded into c5

// pair records: {c0,c1,c2,c3} {c4,c5b,pad,pad} as half2 words -> 32B/pair
__device__ uint4 g_params[NPAIR * 2];

// ---------- helpers ----------
__device__ __forceinline__ __half2 u2h2(unsigned int u) {
    __half2 h; *(unsigned int*)&h = u; return h;
}
__device__ __forceinline__ unsigned int h2u(__half2 h) {
    return *(unsigned int*)&h;
}
__device__ __forceinline__ __half2 hex2(__half2 x) {
    unsigned int y;
    asm("ex2.approx.f16x2 %0, %1;" : "=r"(y) : "r"(h2u(x)));
    return u2h2(y);
}

// ---------- prep: log_softmax(w) + fp16 coefficient records ----------
__global__ void gmm_prep(const float* __restrict__ mu,
                         const float* __restrict__ sigma_log,
                         const float* __restrict__ theta,
                         const float* __restrict__ w,
                         float* __restrict__ out) {
    __shared__ float red[32];
    __shared__ float stage[6][M_MIX];     // scalar c0..c5b per mixture
    const int m    = threadIdx.x;
    const int lane = m & 31;
    const int wid  = m >> 5;

    const float wi = w[m];

    // block max via shuffle
    float v = wi;
    #pragma unroll
    for (int o = 16; o > 0; o >>= 1) v = fmaxf(v, __shfl_xor_sync(~0u, v, o));
    if (lane == 0) red[wid] = v;
    __syncthreads();
    float wmax = red[lane & 31];
    #pragma unroll
    for (int o = 16; o > 0; o >>= 1) wmax = fmaxf(wmax, __shfl_xor_sync(~0u, wmax, o));
    wmax = __shfl_sync(~0u, wmax, 0);
    __syncthreads();

    // block sum(exp) via shuffle
    float e = __expf(wi - wmax);
    #pragma unroll
    for (int o = 16; o > 0; o >>= 1) e += __shfl_xor_sync(~0u, e, o);
    if (lane == 0) red[wid] = e;
    __syncthreads();
    float esum = red[lane & 31];
    #pragma unroll
    for (int o = 16; o > 0; o >>= 1) esum += __shfl_xor_sync(~0u, esum, o);
    esum = __shfl_sync(~0u, esum, 0);

    const float logZ = wmax + __logf(esum);

    const float sl0 = sigma_log[2 * m + 0];
    const float sl1 = sigma_log[2 * m + 1];
    const float a = __expf(-2.0f * sl0);
    const float b = __expf(-2.0f * sl1);
    float s, c;
    __sincosf(theta[m], &s, &c);

    const float g11 = a * c * c + b * s * s;
    const float g12 = (a - b) * c * s;
    const float g22 = a * s * s + b * c * c;
    const float wlog = wi - logZ - sl0 - sl1;

    const float mx = mu[2 * m + 0];
    const float my = mu[2 * m + 1];

    const float L2E = 1.4426950408889634f;

    const float qmu = g11 * mx * mx + 2.0f * g12 * mx * my + g22 * my * my;

    stage[0][m] = -L2E * g11;                          // c0
    stage[1][m] = -L2E * 2.0f * g12;                   // c1
    stage[2][m] = -L2E * g22;                          // c2
    stage[3][m] =  L2E * 2.0f * (g11 * mx + g12 * my); // c3
    stage[4][m] =  L2E * 2.0f * (g12 * mx + g22 * my); // c4
    stage[5][m] =  L2E * (wlog - qmu) + BIAS;          // c5 + BIAS (additive)
    __syncthreads();

    // pack pair records (threads 0..511)
    if (m < NPAIR) {
        const int m0 = 2 * m, m1 = 2 * m + 1;
        uint4 r0, r1;
        r0.x = h2u(__floats2half2_rn(stage[0][m0], stage[0][m1]));
        r0.y = h2u(__floats2half2_rn(stage[1][m0], stage[1][m1]));
        r0.z = h2u(__floats2half2_rn(stage[2][m0], stage[2][m1]));
        r0.w = h2u(__floats2half2_rn(stage[3][m0], stage[3][m1]));
        r1.x = h2u(__floats2half2_rn(stage[4][m0], stage[4][m1]));
        r1.y = h2u(__floats2half2_rn(stage[5][m0], stage[5][m1]));
        r1.z = 0u; r1.w = 0u;
        g_params[2 * m + 0] = r0;
        g_params[2 * m + 1] = r1;
    }

    if (m == 0) out[0] = 0.0f;        // re-zeroed every replay -> deterministic
}

// ---------- hot loop ----------
__global__ void __launch_bounds__(TPB, 3) gmm_main(const float* __restrict__ sample,
                                                   float* __restrict__ out,
                                                   int N) {
    __shared__ __align__(16) uint4 sp[NPAIR * 2];      // 16 KB coefficient records
    __shared__ float partial[8][SAMP_PER_BLK];
    __shared__ float warpsum[8];

    const int tid  = threadIdx.x;
    const int lane = tid & 31;
    const int wid  = tid >> 5;

    // cooperative param load (1024 uint4)
    #pragma unroll
    for (int i = tid; i < NPAIR * 2; i += TPB) sp[i] = g_params[i];
    __syncthreads();

    const int base = blockIdx.x * SAMP_PER_BLK;

    // per-sample fp16x2 monomials (value broadcast to both lanes)
    __half2 hxx[SPT], hxy[SPT], hyy[SPT], hx[SPT], hy[SPT];
    __half2 acch[SPT];
    float accF[SPT];
    #pragma unroll
    for (int k = 0; k < SPT; ++k) {
        const int idx = base + k * 32 + lane;   // coalesced per k
        float x = 0.0f, y = 0.0f;
        if (idx < N) {
            const float2 sv = ((const float2*)sample)[idx];
            x = sv.x; y = sv.y;
        }
        hxx[k] = __float2half2_rn(x * x);
        hxy[k] = __float2half2_rn(x * y);
        hyy[k] = __float2half2_rn(y * y);
        hx[k]  = __float2half2_rn(x);
        hy[k]  = __float2half2_rn(y);
        accF[k] = 0.0f;
    }

    const uint4* ep = sp + wid * EPAIRS * 2;   // this warp's eighth

    // 8 chunks of 8 pairs; fp16x2 accumulate within a chunk, fp32 flush after
    for (int jc = 0; jc < EPAIRS; jc += 8) {
        #pragma unroll
        for (int k = 0; k < SPT; ++k) acch[k] = u2h2(0u);

        #pragma unroll
        for (int jj = 0; jj < 8; ++jj) {
            const uint4 r0 = ep[(jc + jj) * 2 + 0];
            const uint4 r1 = ep[(jc + jj) * 2 + 1];
            const __half2 C0 = u2h2(r0.x), C1 = u2h2(r0.y);
            const __half2 C2 = u2h2(r0.z), C3 = u2h2(r0.w);
            const __half2 C4 = u2h2(r1.x), C5 = u2h2(r1.y);

            #pragma unroll
            for (int k = 0; k < SPT; ++k) {
                __half2 p = __hfma2(C0, hxx[k], C5);   // seed with c5+BIAS
                p = __hfma2(C1, hxy[k], p);
                p = __hfma2(C2, hyy[k], p);
                p = __hfma2(C3, hx[k],  p);
                p = __hfma2(C4, hy[k],  p);            // p in [-14,+2]
                acch[k] = __hadd2(acch[k], hex2(p));
            }
        }

        #pragma unroll
        for (int k = 0; k < SPT; ++k) {
            const float2 f = __half22float2(acch[k]);
            accF[k] += f.x + f.y;
        }
    }

    #pragma unroll
    for (int k = 0; k < SPT; ++k)
        partial[wid][k * 32 + lane] = accF[k];
    __syncthreads();

    // combine eighths; one sample per thread (tid < 160)
    float nll_i = 0.0f;
    if (tid < SAMP_PER_BLK) {
        const int sidx = base + tid;
        if (sidx < N) {
            float tot = 0.0f;
            #pragma unroll
            for (int q = 0; q < 8; ++q) tot += partial[q][tid];
            // tot = 2^BIAS * true_sum
            nll_i = 0.69314718055994531f * (BIAS - __log2f(tot));
        }
    }

    // block reduce
    #pragma unroll
    for (int o = 16; o > 0; o >>= 1)
        nll_i += __shfl_xor_sync(0xffffffffu, nll_i, o);
    if (lane == 0) warpsum[wid] = nll_i;
    __syncthreads();

    if (tid == 0) {
        float v = 0.0f;
        #pragma unroll
        for (int i = 0; i < 8; ++i) v += warpsum[i];
        atomicAdd(out, v);
    }
}

extern "C" void kernel_launch(void* const* d_in, const int* in_sizes, int n_in,
                              void* d_out, int out_size) {
    const float* sample    = (const float*)d_in[0];
    const float* mu        = (const float*)d_in[1];
    const float* sigma_log = (const float*)d_in[2];
    const float* theta     = (const float*)d_in[3];
    const float* w         = (const float*)d_in[4];
    float* out = (float*)d_out;

    const int N = in_sizes[0] / 2;
    const int grid = (N + SAMP_PER_BLK - 1) / SAMP_PER_BLK;

    gmm_prep<<<1, M_MIX>>>(mu, sigma_log, theta, w, out);
    gmm_main<<<grid, TPB>>>(sample, out, N);
}

// round 14
// speedup vs baseline: 1.0949x; 1.0828x over previous
#include <cuda_runtime.h>
#include <cuda_fp16.h>
#include <cstdint>

// GaussianMixture NLL: N=65536 samples (2D), M=1024 mixtures.  SPARSITY == 0.
// nll = -sum_n log( sum_m exp(wlog_m - qf(n,m)) )
//
// v14: hot loop = R12 (FMA-rt2 floor: 5 HFMA2 + HADD2 + ex2.f16x2 per
//  (mixture-pair, sample) unit; 18.4us measured — at its pipe floor).
//  This round attacks the 4.3us prep/launch overhead: prep parallelized to
//  8 blocks x 64 threads (1 thread = 1 mixture pair), with the w-softmax
//  logZ computed redundantly per block (16 w values/thread, 2-warp reduce).

#define M_MIX   1024
#define NPAIR   (M_MIX / 2)      // 512
#define EPAIRS  (NPAIR / 8)      // 64 pairs per warp-eighth
#define TPB     256
#define SPT     4
#define SAMP_PER_BLK  128        // 32 lanes * 4 samples
#define BIAS    8.0f             // log2-domain bias folded into c5

#define PREP_BLOCKS  8
#define PREP_TPB     64          // 1 thread = 1 pair; 8*64 = 512 pairs

// pair records: {c0,c1,c2,c3} {c4,c5b,pad,pad} as half2 words -> 32B/pair
__device__ uint4 g_params[NPAIR * 2];

// ---------- helpers ----------
__device__ __forceinline__ __half2 u2h2(unsigned int u) {
    __half2 h; *(unsigned int*)&h = u; return h;
}
__device__ __forceinline__ unsigned int h2u(__half2 h) {
    return *(unsigned int*)&h;
}
__device__ __forceinline__ __half2 hex2(__half2 x) {
    unsigned int y;
    asm("ex2.approx.f16x2 %0, %1;" : "=r"(y) : "r"(h2u(x)));
    return u2h2(y);
}

// ---------- per-mixture coefficient computation ----------
__device__ __forceinline__ void mix_coeffs(int m, float logZ,
                                           const float* __restrict__ mu,
                                           const float* __restrict__ sigma_log,
                                           const float* __restrict__ theta,
                                           const float* __restrict__ w,
                                           float* C /*[6]*/) {
    const float wi  = w[m];
    const float sl0 = sigma_log[2 * m + 0];
    const float sl1 = sigma_log[2 * m + 1];
    const float a = __expf(-2.0f * sl0);
    const float b = __expf(-2.0f * sl1);
    float s, c;
    __sincosf(theta[m], &s, &c);

    const float g11 = a * c * c + b * s * s;
    const float g12 = (a - b) * c * s;
    const float g22 = a * s * s + b * c * c;
    const float wlog = wi - logZ - sl0 - sl1;

    const float mx = mu[2 * m + 0];
    const float my = mu[2 * m + 1];

    const float L2E = 1.4426950408889634f;
    const float qmu = g11 * mx * mx + 2.0f * g12 * mx * my + g22 * my * my;

    C[0] = -L2E * g11;
    C[1] = -L2E * 2.0f * g12;
    C[2] = -L2E * g22;
    C[3] =  L2E * 2.0f * (g11 * mx + g12 * my);
    C[4] =  L2E * 2.0f * (g12 * mx + g22 * my);
    C[5] =  L2E * (wlog - qmu) + BIAS;
}

// ---------- prep: 8 blocks, redundant per-block softmax, 1 thread = 1 pair ----------
__global__ void __launch_bounds__(PREP_TPB) gmm_prep(const float* __restrict__ mu,
                                                     const float* __restrict__ sigma_log,
                                                     const float* __restrict__ theta,
                                                     const float* __restrict__ w,
                                                     float* __restrict__ out) {
    __shared__ float red[2];
    const int tid  = threadIdx.x;            // 0..63
    const int lane = tid & 31;
    const int wrp  = tid >> 5;               // 0..1

    // each thread folds 16 of the 1024 w values
    float wv[16];
    float lmax = -1e30f;
    #pragma unroll
    for (int i = 0; i < 16; ++i) {
        wv[i] = w[tid + i * PREP_TPB];
        lmax = fmaxf(lmax, wv[i]);
    }
    #pragma unroll
    for (int o = 16; o > 0; o >>= 1) lmax = fmaxf(lmax, __shfl_xor_sync(~0u, lmax, o));
    if (lane == 0) red[wrp] = lmax;
    __syncthreads();
    const float wmax = fmaxf(red[0], red[1]);
    __syncthreads();

    float lsum = 0.0f;
    #pragma unroll
    for (int i = 0; i < 16; ++i) lsum += __expf(wv[i] - wmax);
    #pragma unroll
    for (int o = 16; o > 0; o >>= 1) lsum += __shfl_xor_sync(~0u, lsum, o);
    if (lane == 0) red[wrp] = lsum;
    __syncthreads();
    const float logZ = wmax + __logf(red[0] + red[1]);

    // this thread's mixture pair
    const int p  = blockIdx.x * PREP_TPB + tid;   // 0..511
    const int m0 = 2 * p, m1 = 2 * p + 1;

    float C0[6], C1[6];
    mix_coeffs(m0, logZ, mu, sigma_log, theta, w, C0);
    mix_coeffs(m1, logZ, mu, sigma_log, theta, w, C1);

    uint4 r0, r1;
    r0.x = h2u(__floats2half2_rn(C0[0], C1[0]));
    r0.y = h2u(__floats2half2_rn(C0[1], C1[1]));
    r0.z = h2u(__floats2half2_rn(C0[2], C1[2]));
    r0.w = h2u(__floats2half2_rn(C0[3], C1[3]));
    r1.x = h2u(__floats2half2_rn(C0[4], C1[4]));
    r1.y = h2u(__floats2half2_rn(C0[5], C1[5]));
    r1.z = 0u; r1.w = 0u;
    g_params[2 * p + 0] = r0;
    g_params[2 * p + 1] = r1;

    if (blockIdx.x == 0 && tid == 0) out[0] = 0.0f;   // re-zeroed every replay
}

// ---------- hot loop (R12 config — at FMA-pipe floor) ----------
__global__ void __launch_bounds__(TPB, 4) gmm_main(const float* __restrict__ sample,
                                                   float* __restrict__ out,
                                                   int N) {
    __shared__ __align__(16) uint4 sp[NPAIR * 2];      // 16 KB coefficient records
    __shared__ float partial[8][SAMP_PER_BLK];
    __shared__ float warpsum[8];

    const int tid  = threadIdx.x;
    const int lane = tid & 31;
    const int wid  = tid >> 5;

    // cooperative param load (1024 uint4)
    #pragma unroll
    for (int i = tid; i < NPAIR * 2; i += TPB) sp[i] = g_params[i];
    __syncthreads();

    const int base = blockIdx.x * SAMP_PER_BLK;

    // per-sample fp16x2 monomials (value broadcast to both lanes)
    __half2 hxx[SPT], hxy[SPT], hyy[SPT], hx[SPT], hy[SPT];
    __half2 acch[SPT];
    float accF[SPT];
    #pragma unroll
    for (int k = 0; k < SPT; ++k) {
        const int idx = base + k * 32 + lane;   // coalesced per k
        float x = 0.0f, y = 0.0f;
        if (idx < N) {
            const float2 sv = ((const float2*)sample)[idx];
            x = sv.x; y = sv.y;
        }
        hxx[k] = __float2half2_rn(x * x);
        hxy[k] = __float2half2_rn(x * y);
        hyy[k] = __float2half2_rn(y * y);
        hx[k]  = __float2half2_rn(x);
        hy[k]  = __float2half2_rn(y);
        accF[k] = 0.0f;
    }

    const uint4* ep = sp + wid * EPAIRS * 2;   // this warp's eighth

    // 8 chunks of 8 pairs; fp16x2 accumulate within a chunk, fp32 flush after
    for (int jc = 0; jc < EPAIRS; jc += 8) {
        #pragma unroll
        for (int k = 0; k < SPT; ++k) acch[k] = u2h2(0u);

        #pragma unroll
        for (int jj = 0; jj < 8; ++jj) {
            const uint4 r0 = ep[(jc + jj) * 2 + 0];
            const uint4 r1 = ep[(jc + jj) * 2 + 1];
            const __half2 C0 = u2h2(r0.x), C1 = u2h2(r0.y);
            const __half2 C2 = u2h2(r0.z), C3 = u2h2(r0.w);
            const __half2 C4 = u2h2(r1.x), C5 = u2h2(r1.y);

            #pragma unroll
            for (int k = 0; k < SPT; ++k) {
                __half2 p = __hfma2(C0, hxx[k], C5);   // seed with c5+BIAS
                p = __hfma2(C1, hxy[k], p);
                p = __hfma2(C2, hyy[k], p);
                p = __hfma2(C3, hx[k],  p);
                p = __hfma2(C4, hy[k],  p);            // p in [-14,+2]
                acch[k] = __hadd2(acch[k], hex2(p));
            }
        }

        #pragma unroll
        for (int k = 0; k < SPT; ++k) {
            const float2 f = __half22float2(acch[k]);
            accF[k] += f.x + f.y;
        }
    }

    #pragma unroll
    for (int k = 0; k < SPT; ++k)
        partial[wid][k * 32 + lane] = accF[k];
    __syncthreads();

    // combine eighths; one sample per thread (tid < 128)
    float nll_i = 0.0f;
    if (tid < SAMP_PER_BLK) {
        const int sidx = base + tid;
        if (sidx < N) {
            float tot = 0.0f;
            #pragma unroll
            for (int q = 0; q < 8; ++q) tot += partial[q][tid];
            // tot = 2^BIAS * true_sum
            nll_i = 0.69314718055994531f * (BIAS - __log2f(tot));
        }
    }

    // block reduce
    #pragma unroll
    for (int o = 16; o > 0; o >>= 1)
        nll_i += __shfl_xor_sync(0xffffffffu, nll_i, o);
    if (lane == 0) warpsum[wid] = nll_i;
    __syncthreads();

    if (tid == 0) {
        float v = 0.0f;
        #pragma unroll
        for (int i = 0; i < 8; ++i) v += warpsum[i];
        atomicAdd(out, v);
    }
}

extern "C" void kernel_launch(void* const* d_in, const int* in_sizes, int n_in,
                              void* d_out, int out_size) {
    const float* sample    = (const float*)d_in[0];
    const float* mu        = (const float*)d_in[1];
    const float* sigma_log = (const float*)d_in[2];
    const float* theta     = (const float*)d_in[3];
    const float* w         = (const float*)d_in[4];
    float* out = (float*)d_out;

    const int N = in_sizes[0] / 2;
    const int grid = (N + SAMP_PER_BLK - 1) / SAMP_PER_BLK;

    gmm_prep<<<PREP_BLOCKS, PREP_TPB>>>(mu, sigma_log, theta, w, out);
    gmm_main<<<grid, TPB>>>(sample, out, N);
}

// round 15
// speedup vs baseline: 1.3795x; 1.2600x over previous
#include <cuda_runtime.h>
#include <cuda_fp16.h>
#include <cstdint>

// GaussianMixture NLL: N=65536 samples (2D), M=1024 mixtures.  SPARSITY == 0.
// nll = -sum_n log( sum_m exp(wlog_m - qf(n,m)) )
//
// v15: tensor-core poly evaluation.
//   poly[n,m] = A[n,:] . B[:,m],  A = [xx,xy,yy,x,y,1,0,0] (K=8 monomials),
//   B = [c0,c1,c2,c3,c4,c5+BIAS,0,0]  (log2-scaled coefficients, fp16).
//   One mma.sync.m16n8k8.f16 computes a 16x8 poly tile -> the 5.2M HFMA2
//   leave the FMA pipe; epilogue = 2x ex2.approx.f16x2 (MUFU) + 2x HADD2
//   per tile.  MUFU (14.2K cyc) becomes the binding pipe.
//   Block: 256 thr = 8 warps x 128 mixtures (16 B-tiles), 64 samples
//   (4 A-tiles); grid = 1024 (N divides exactly).  B stored in fragment
//   order (lane-linear LDS); fp16 accumulation flushed to fp32 every
//   8 mixture-tiles (validated 3.2e-4 scheme).

#define M_MIX   1024
#define TPB     256
#define SAMP_PER_BLK  64
#define BIAS    8.0f

#define PREP_BLOCKS  8
#define PREP_TPB     64

// per-mixture coefficient record in B-fragment order:
//   word0 = (c0,c1)  word1 = (c2,c3)  word2 = (c4,c5b)  word3 = (0,0)
__device__ uint4 g_params[M_MIX];

// ---------- helpers ----------
__device__ __forceinline__ __half2 u2h2(unsigned int u) {
    __half2 h; *(unsigned int*)&h = u; return h;
}
__device__ __forceinline__ unsigned int h2u(__half2 h) {
    return *(unsigned int*)&h;
}
__device__ __forceinline__ unsigned int hex2u(unsigned int x) {
    unsigned int y;
    asm("ex2.approx.f16x2 %0, %1;" : "=r"(y) : "r"(x));
    return y;
}
__device__ __forceinline__ unsigned int hadd2u(unsigned int a, unsigned int b) {
    unsigned int y;
    asm("add.rn.f16x2 %0, %1, %2;" : "=r"(y) : "r"(a), "r"(b));
    return y;
}
// m16n8k8 f16 MMA, C = 0
__device__ __forceinline__ void mma16n8k8(unsigned int& d0, unsigned int& d1,
                                          unsigned int a0, unsigned int a1,
                                          unsigned int b0) {
    unsigned int z = 0u;
    asm("mma.sync.aligned.m16n8k8.row.col.f16.f16.f16.f16 "
        "{%0,%1}, {%2,%3}, {%4}, {%5,%6};"
        : "=r"(d0), "=r"(d1)
        : "r"(a0), "r"(a1), "r"(b0), "r"(z), "r"(z));
}

// ---------- per-mixture coefficient computation ----------
__device__ __forceinline__ void mix_coeffs(int m, float logZ,
                                           const float* __restrict__ mu,
                                           const float* __restrict__ sigma_log,
                                           const float* __restrict__ theta,
                                           const float* __restrict__ w,
                                           float* C /*[6]*/) {
    const float wi  = w[m];
    const float sl0 = sigma_log[2 * m + 0];
    const float sl1 = sigma_log[2 * m + 1];
    const float a = __expf(-2.0f * sl0);
    const float b = __expf(-2.0f * sl1);
    float s, c;
    __sincosf(theta[m], &s, &c);

    const float g11 = a * c * c + b * s * s;
    const float g12 = (a - b) * c * s;
    const float g22 = a * s * s + b * c * c;
    const float wlog = wi - logZ - sl0 - sl1;

    const float mx = mu[2 * m + 0];
    const float my = mu[2 * m + 1];

    const float L2E = 1.4426950408889634f;
    const float qmu = g11 * mx * mx + 2.0f * g12 * mx * my + g22 * my * my;

    C[0] = -L2E * g11;
    C[1] = -L2E * 2.0f * g12;
    C[2] = -L2E * g22;
    C[3] =  L2E * 2.0f * (g11 * mx + g12 * my);
    C[4] =  L2E * 2.0f * (g12 * mx + g22 * my);
    C[5] =  L2E * (wlog - qmu) + BIAS;
}

// ---------- prep: 8 blocks, redundant per-block softmax, 1 thread = 2 mixtures ----------
__global__ void __launch_bounds__(PREP_TPB) gmm_prep(const float* __restrict__ mu,
                                                     const float* __restrict__ sigma_log,
                                                     const float* __restrict__ theta,
                                                     const float* __restrict__ w,
                                                     float* __restrict__ out) {
    __shared__ float red[2];
    const int tid  = threadIdx.x;            // 0..63
    const int lane = tid & 31;
    const int wrp  = tid >> 5;               // 0..1

    // each thread folds 16 of the 1024 w values
    float wv[16];
    float lmax = -1e30f;
    #pragma unroll
    for (int i = 0; i < 16; ++i) {
        wv[i] = w[tid + i * PREP_TPB];
        lmax = fmaxf(lmax, wv[i]);
    }
    #pragma unroll
    for (int o = 16; o > 0; o >>= 1) lmax = fmaxf(lmax, __shfl_xor_sync(~0u, lmax, o));
    if (lane == 0) red[wrp] = lmax;
    __syncthreads();
    const float wmax = fmaxf(red[0], red[1]);
    __syncthreads();

    float lsum = 0.0f;
    #pragma unroll
    for (int i = 0; i < 16; ++i) lsum += __expf(wv[i] - wmax);
    #pragma unroll
    for (int o = 16; o > 0; o >>= 1) lsum += __shfl_xor_sync(~0u, lsum, o);
    if (lane == 0) red[wrp] = lsum;
    __syncthreads();
    const float logZ = wmax + __logf(red[0] + red[1]);

    const int p  = blockIdx.x * PREP_TPB + tid;   // 0..511
    #pragma unroll
    for (int h = 0; h < 2; ++h) {
        const int m = 2 * p + h;
        float C[6];
        mix_coeffs(m, logZ, mu, sigma_log, theta, w, C);
        uint4 r;
        r.x = h2u(__floats2half2_rn(C[0], C[1]));
        r.y = h2u(__floats2half2_rn(C[2], C[3]));
        r.z = h2u(__floats2half2_rn(C[4], C[5]));
        r.w = 0u;
        g_params[m] = r;
    }

    if (blockIdx.x == 0 && tid == 0) out[0] = 0.0f;   // re-zeroed every replay
}

// ---------- hot loop: tensor-core poly + MUFU ex2 epilogue ----------
__global__ void __launch_bounds__(TPB, 3) gmm_main(const float* __restrict__ sample,
                                                   float* __restrict__ out,
                                                   int N) {
    __shared__ __align__(16) uint4 spB[M_MIX];          // 16 KB B records
    __shared__ __align__(16) uint4 smA[SAMP_PER_BLK];   // 1 KB A monomials
    __shared__ float partial[8][SAMP_PER_BLK];
    __shared__ float warpsum[8];

    const int tid  = threadIdx.x;
    const int lane = tid & 31;
    const int wid  = tid >> 5;

    // cooperative B load
    #pragma unroll
    for (int i = tid; i < M_MIX; i += TPB) spB[i] = g_params[i];

    const int base = blockIdx.x * SAMP_PER_BLK;

    // stage A monomials: [xx,xy,yy,x,y,1,0,0] fp16 per sample
    if (tid < SAMP_PER_BLK) {
        const int idx = base + tid;
        float x = 0.0f, y = 0.0f;
        if (idx < N) {
            const float2 sv = ((const float2*)sample)[idx];
            x = sv.x; y = sv.y;
        }
        uint4 r;
        r.x = h2u(__floats2half2_rn(x * x, x * y));
        r.y = h2u(__floats2half2_rn(y * y, x));
        r.z = h2u(__floats2half2_rn(y, 1.0f));
        r.w = 0u;
        smA[tid] = r;
    }
    __syncthreads();

    const unsigned int* A32 = (const unsigned int*)smA;
    const unsigned int* B32 = (const unsigned int*)spB;

    // A fragments: 4 sample-tiles of 16 rows; lane-linear, conflict-free
    unsigned int a0[4], a1[4];
    #pragma unroll
    for (int st = 0; st < 4; ++st) {
        a0[st] = A32[st * 64 + lane];        // row = st*16 + lane/4
        a1[st] = A32[st * 64 + 32 + lane];   // row + 8
    }

    float accFA[4] = {0.f, 0.f, 0.f, 0.f};
    float accFB[4] = {0.f, 0.f, 0.f, 0.f};

    const int bbase = wid * 512;             // this warp's 128 mixtures (16 tiles)

    #pragma unroll
    for (int tc = 0; tc < 2; ++tc) {         // 2 chunks of 8 mixture-tiles
        unsigned int hA[4] = {0u, 0u, 0u, 0u};
        unsigned int hB[4] = {0u, 0u, 0u, 0u};

        #pragma unroll
        for (int tt = 0; tt < 8; ++tt) {
            const unsigned int b = B32[bbase + (tc * 8 + tt) * 32 + lane];  // lane-linear
            #pragma unroll
            for (int st = 0; st < 4; ++st) {
                unsigned int d0, d1;
                mma16n8k8(d0, d1, a0[st], a1[st], b);   // poly tile, log2-biased
                hA[st] = hadd2u(hA[st], hex2u(d0));
                hB[st] = hadd2u(hB[st], hex2u(d1));
            }
        }

        #pragma unroll
        for (int st = 0; st < 4; ++st) {     // flush fp16 chunk to fp32
            const float2 fa = __half22float2(u2h2(hA[st]));
            const float2 fb = __half22float2(u2h2(hB[st]));
            accFA[st] += fa.x + fa.y;
            accFB[st] += fb.x + fb.y;
        }
    }

    // reduce cols within each 4-lane row group
    #pragma unroll
    for (int st = 0; st < 4; ++st) {
        float vA = accFA[st], vB = accFB[st];
        vA += __shfl_xor_sync(~0u, vA, 1);
        vA += __shfl_xor_sync(~0u, vA, 2);
        vB += __shfl_xor_sync(~0u, vB, 1);
        vB += __shfl_xor_sync(~0u, vB, 2);
        if ((lane & 3) == 0) {
            const int r = lane >> 2;
            partial[wid][st * 16 + r]     = vA;
            partial[wid][st * 16 + 8 + r] = vB;
        }
    }
    __syncthreads();

    // combine warps; one sample per thread (tid < 64)
    float nll_i = 0.0f;
    if (tid < SAMP_PER_BLK) {
        const int sidx = base + tid;
        if (sidx < N) {
            float tot = 0.0f;
            #pragma unroll
            for (int q = 0; q < 8; ++q) tot += partial[q][tid];
            // tot = 2^BIAS * true_sum
            nll_i = 0.69314718055994531f * (BIAS - __log2f(tot));
        }
    }

    // block reduce
    #pragma unroll
    for (int o = 16; o > 0; o >>= 1)
        nll_i += __shfl_xor_sync(0xffffffffu, nll_i, o);
    if (lane == 0) warpsum[wid] = nll_i;
    __syncthreads();

    if (tid == 0) {
        float v = 0.0f;
        #pragma unroll
        for (int i = 0; i < 8; ++i) v += warpsum[i];
        atomicAdd(out, v);
    }
}

extern "C" void kernel_launch(void* const* d_in, const int* in_sizes, int n_in,
                              void* d_out, int out_size) {
    const float* sample    = (const float*)d_in[0];
    const float* mu        = (const float*)d_in[1];
    const float* sigma_log = (const float*)d_in[2];
    const float* theta     = (const float*)d_in[3];
    const float* w         = (const float*)d_in[4];
    float* out = (float*)d_out;

    const int N = in_sizes[0] / 2;
    const int grid = (N + SAMP_PER_BLK - 1) / SAMP_PER_BLK;

    gmm_prep<<<PREP_BLOCKS, PREP_TPB>>>(mu, sigma_log, theta, w, out);
    gmm_main<<<grid, TPB>>>(sample, out, N);
}